// round 14
// baseline (speedup 1.0000x reference)
#include <cuda_runtime.h>
#include <cstdint>

// NeuralHashVoxel: 64^3-Morton counting-sorted queries + per-level hash probing.
// Levels 0-1 (scattered lanes): 4-4 validity-gated probing, STREAMING loads
// (__ldcs) so single-use random sectors don't thrash L1 (coarse-level lines are
// the reusable ones). Levels 2-5 (post-sort coalesced): single-round 8-probe,
// normal __ldg. Pipeline: 4 launches; g_hist zeroed by nhv's tail (.bss at t=0).
//
// Inputs: d_in[0] query_points f32 (N,3) in [0,50); d_in[1] features f32 (6,524288,8);
//         d_in[2] feature_indexs i32 (6,4194304) (-1 empty else [0,T)).
// Output: f32 (N,8).

#define NHV_L 6
#define NHV_T 524288
#define NHV_B 4194304u
#define NHV_BMASK 4194303u
#define P0 73856093u
#define P1 19349669u
#define P2 83492791u

#define NQ_MAX (1u << 20)
#define GRID1D 64
#define NBINS (GRID1D * GRID1D * GRID1D)     // 262144
#define SCAN_BLOCK_BINS 1024
#define SCAN_NBLK (NBINS / SCAN_BLOCK_BINS)  // 256

__device__ uint32_t g_hist[NBINS];
__device__ uint32_t g_blocksum[SCAN_NBLK];
__device__ uint32_t g_bsum_prefix[SCAN_NBLK];  // exclusive prefix of g_blocksum
__device__ uint32_t g_done_counter;
__device__ float4   g_qsort[NQ_MAX];           // xyz = point, w = orig index bits

static __device__ __forceinline__ uint32_t expand3(uint32_t x) {
    x &= 0x3FFu;
    x = (x | (x << 16)) & 0x030000FFu;
    x = (x | (x << 8))  & 0x0300F00Fu;
    x = (x | (x << 4))  & 0x030C30C3u;
    x = (x | (x << 2))  & 0x09249249u;
    return x;
}

static __device__ __forceinline__ uint32_t bin_of(float x, float y, float z) {
    const float sc = (float)GRID1D / 50.0f;
    int bx = (int)(x * sc), by = (int)(y * sc), bz = (int)(z * sc);
    bx = min(max(bx, 0), GRID1D - 1);
    by = min(max(by, 0), GRID1D - 1);
    bz = min(max(bz, 0), GRID1D - 1);
    return expand3((uint32_t)bx) | (expand3((uint32_t)by) << 1) | (expand3((uint32_t)bz) << 2);
}

__global__ void hist_kernel(const float* __restrict__ qp, int n) {
    int i = blockIdx.x * blockDim.x + threadIdx.x;
    if (i >= n) return;
    float x = qp[3 * i], y = qp[3 * i + 1], z = qp[3 * i + 2];
    atomicAdd(&g_hist[bin_of(x, y, z)], 1u);
}

// Per-superblock (1024 bins) exclusive scan; the LAST block to finish also
// computes the exclusive prefix over the 256 superblock sums.
__global__ void __launch_bounds__(SCAN_BLOCK_BINS) scan_blocks_kernel() {
    __shared__ uint32_t sh[SCAN_BLOCK_BINS];
    __shared__ int is_last;
    int t = threadIdx.x;
    int b = blockIdx.x * SCAN_BLOCK_BINS + t;
    uint32_t v = g_hist[b];
    sh[t] = v;
    __syncthreads();
    #pragma unroll
    for (int off = 1; off < SCAN_BLOCK_BINS; off <<= 1) {
        uint32_t add = (t >= off) ? sh[t - off] : 0u;
        __syncthreads();
        sh[t] += add;
        __syncthreads();
    }
    g_hist[b] = sh[t] - v;  // exclusive within superblock

    // Writer of g_blocksum fences + signals (store->fence->atomic, same thread).
    if (t == SCAN_BLOCK_BINS - 1) {
        g_blocksum[blockIdx.x] = sh[t];
        __threadfence();
        is_last = (atomicAdd(&g_done_counter, 1u) == (uint32_t)(SCAN_NBLK - 1));
    }
    __syncthreads();
    if (is_last) {
        __shared__ uint32_t bs[SCAN_NBLK];
        if (t < SCAN_NBLK) bs[t] = g_blocksum[t];
        __syncthreads();
        #pragma unroll
        for (int off = 1; off < SCAN_NBLK; off <<= 1) {
            uint32_t add = (t < SCAN_NBLK && t >= off) ? bs[t - off] : 0u;
            __syncthreads();
            if (t < SCAN_NBLK) bs[t] += add;
            __syncthreads();
        }
        if (t < SCAN_NBLK) g_bsum_prefix[t] = bs[t] - g_blocksum[t];  // exclusive
    }
}

__global__ void scatter_kernel(const float* __restrict__ qp, int n) {
    int i = blockIdx.x * blockDim.x + threadIdx.x;
    if (i >= n) return;
    float x = qp[3 * i], y = qp[3 * i + 1], z = qp[3 * i + 2];
    uint32_t bin = bin_of(x, y, z);
    uint32_t pos = atomicAdd(&g_hist[bin], 1u) + __ldg(&g_bsum_prefix[bin >> 10]);
    g_qsort[pos] = make_float4(x, y, z, __int_as_float(i));
}

// STREAM=true -> __ldcs (evict-first streaming: single-use random sectors must
// not displace reusable coarse-level lines in L1).
template <bool STREAM>
static __device__ __forceinline__ int probe(const int* __restrict__ htab,
                                            uint32_t key) {
    const int* p = htab + (key & NHV_BMASK);
    return STREAM ? __ldcs(p) : __ldg(p);
}

template <bool STREAM>
static __device__ __forceinline__ float4 fload(const float4* __restrict__ p) {
    return STREAM ? __ldcs(p) : __ldg(p);
}

// One resolution level. GATE: probe 4 corners, test, then the other 4
// (pays only when lanes are spatially scattered, i.e. fine levels).
template <bool GATE>
static __device__ __forceinline__ void do_level(
    float sx, float sy, float sz,
    const int* __restrict__ htab,
    const float* __restrict__ ftab,
    float* __restrict__ acc)
{
    const float bx = floorf(sx), by = floorf(sy), bz = floorf(sz);
    const float tx = sx - bx, ty = sy - by, tz = sz - bz;

    const uint32_t ix = (uint32_t)(int)bx;
    const uint32_t iy = (uint32_t)(int)by;
    const uint32_t iz = (uint32_t)(int)bz;
    const uint32_t h0 = ix * P0 + iy * P1 + iz * P2;

    // corner k: key = h0 + (k&4 ? P0) + (k&2 ? P1) + (k&1 ? P2)
    int idx[8];
    if (GATE) {
        idx[0] = probe<true>(htab, h0);
        idx[1] = probe<true>(htab, h0 + P2);
        idx[2] = probe<true>(htab, h0 + P1);
        idx[3] = probe<true>(htab, h0 + P1 + P2);
        if ((idx[0] | idx[1] | idx[2] | idx[3]) < 0) return;
        idx[4] = probe<true>(htab, h0 + P0);
        idx[5] = probe<true>(htab, h0 + P0 + P2);
        idx[6] = probe<true>(htab, h0 + P0 + P1);
        idx[7] = probe<true>(htab, h0 + P0 + P1 + P2);
        if ((idx[4] | idx[5] | idx[6] | idx[7]) < 0) return;
    } else {
        #pragma unroll
        for (int k = 0; k < 8; k++) {
            uint32_t key = h0;
            if (k & 4) key += P0;
            if (k & 2) key += P1;
            if (k & 1) key += P2;
            idx[k] = probe<false>(htab, key);
        }
        if ((idx[0] | idx[1] | idx[2] | idx[3] |
             idx[4] | idx[5] | idx[6] | idx[7]) < 0) return;
    }

    const float wxa[2] = { 1.f - tx, tx };
    const float wya[2] = { 1.f - ty, ty };
    const float wza[2] = { 1.f - tz, tz };

    #pragma unroll
    for (int k = 0; k < 8; k++) {
        const float w = wxa[(k >> 2) & 1] * wya[(k >> 1) & 1] * wza[k & 1];
        uint32_t id = (uint32_t)idx[k];
        id = (id < NHV_T) ? id : (NHV_T - 1u);
        const float4* fp = (const float4*)(ftab + ((size_t)id << 3));
        float4 a = fload<GATE>(fp);
        float4 b = fload<GATE>(fp + 1);
        acc[0] = fmaf(w, a.x, acc[0]);
        acc[1] = fmaf(w, a.y, acc[1]);
        acc[2] = fmaf(w, a.z, acc[2]);
        acc[3] = fmaf(w, a.w, acc[3]);
        acc[4] = fmaf(w, b.x, acc[4]);
        acc[5] = fmaf(w, b.y, acc[5]);
        acc[6] = fmaf(w, b.z, acc[6]);
        acc[7] = fmaf(w, b.w, acc[7]);
    }
}

__global__ void __launch_bounds__(256, 6) nhv_kernel(
    const float* __restrict__ feats,
    const int*   __restrict__ fidx,
    float* __restrict__ out,
    int n_query)
{
    int i = blockIdx.x * blockDim.x + threadIdx.x;

    // Tail duty: re-zero sort state for the NEXT call/replay (safe: this kernel
    // runs after scatter; .bss guarantees zeros on the very first call).
    if (i < NBINS) g_hist[i] = 0u;
    if (i == 0) g_done_counter = 0u;

    if (i >= n_query) return;

    const float4 q = g_qsort[i];
    const uint32_t n = (uint32_t)__float_as_int(q.w);

    float acc[8] = {0.f, 0.f, 0.f, 0.f, 0.f, 0.f, 0.f, 0.f};

    const size_t HB = (size_t)NHV_B;
    const size_t FT = (size_t)NHV_T * 8;

    // lev 0..5, scale = 4 / 2^lev; GATE (+streaming) only on scattered fine levels.
    do_level<true >(q.x * 4.f,    q.y * 4.f,    q.z * 4.f,    fidx,          feats,          acc);
    do_level<true >(q.x * 2.f,    q.y * 2.f,    q.z * 2.f,    fidx + HB,     feats + FT,     acc);
    do_level<false>(q.x * 1.f,    q.y * 1.f,    q.z * 1.f,    fidx + 2*HB,   feats + 2*FT,   acc);
    do_level<false>(q.x * 0.5f,   q.y * 0.5f,   q.z * 0.5f,   fidx + 3*HB,   feats + 3*FT,   acc);
    do_level<false>(q.x * 0.25f,  q.y * 0.25f,  q.z * 0.25f,  fidx + 4*HB,   feats + 4*FT,   acc);
    do_level<false>(q.x * 0.125f, q.y * 0.125f, q.z * 0.125f, fidx + 5*HB,   feats + 5*FT,   acc);

    float4* o = (float4*)(out + ((size_t)n << 3));
    o[0] = make_float4(acc[0], acc[1], acc[2], acc[3]);
    o[1] = make_float4(acc[4], acc[5], acc[6], acc[7]);
}

extern "C" void kernel_launch(void* const* d_in, const int* in_sizes, int n_in,
                              void* d_out, int out_size)
{
    const float* qp    = (const float*)d_in[0];
    const float* feats = (const float*)d_in[1];
    const int*   fidx  = (const int*)d_in[2];
    float* out = (float*)d_out;

    int n_query = in_sizes[0] / 3;
    int threads = 256;
    int blocks = (n_query + threads - 1) / threads;

    hist_kernel<<<blocks, threads>>>(qp, n_query);
    scan_blocks_kernel<<<SCAN_NBLK, SCAN_BLOCK_BINS>>>();
    scatter_kernel<<<blocks, threads>>>(qp, n_query);
    nhv_kernel<<<blocks, threads>>>(feats, fidx, out, n_query);
}

// round 15
// speedup vs baseline: 1.0180x; 1.0180x over previous
#include <cuda_runtime.h>
#include <cstdint>

// NeuralHashVoxel: 128^3-Morton counting-sorted queries + per-level hash probing.
// Levels 0-1 (scattered lanes): 4-4 validity-gated probing (E[probes]=5.64).
// Levels 2-5 (post-sort coalesced): single-round 8-probe. All loads __ldg
// (R14 lesson: __ldcs streaming LOST 6 us — fine-level lines have L1 reuse).
// Pipeline: 4 launches (hist, scan, scatter, nhv); nhv tail re-zeros g_hist.
//
// Inputs: d_in[0] query_points f32 (N,3) in [0,50); d_in[1] features f32 (6,524288,8);
//         d_in[2] feature_indexs i32 (6,4194304) (-1 empty else [0,T)).
// Output: f32 (N,8).

#define NHV_L 6
#define NHV_T 524288
#define NHV_B 4194304u
#define NHV_BMASK 4194303u
#define P0 73856093u
#define P1 19349669u
#define P2 83492791u

#define NQ_MAX (1u << 20)
#define GRID1D 128
#define NBINS (GRID1D * GRID1D * GRID1D)     // 2097152 (21-bit Morton)
#define SB_BINS 2048                          // bins per scan superblock
#define SCAN_THREADS 1024                     // 2 bins per thread
#define SCAN_NBLK (NBINS / SB_BINS)           // 1024

__device__ uint32_t g_hist[NBINS];
__device__ uint32_t g_blocksum[SCAN_NBLK];
__device__ uint32_t g_bsum_prefix[SCAN_NBLK];  // exclusive prefix of g_blocksum
__device__ uint32_t g_done_counter;
__device__ float4   g_qsort[NQ_MAX];           // xyz = point, w = orig index bits

static __device__ __forceinline__ uint32_t expand3(uint32_t x) {
    x &= 0x3FFu;
    x = (x | (x << 16)) & 0x030000FFu;
    x = (x | (x << 8))  & 0x0300F00Fu;
    x = (x | (x << 4))  & 0x030C30C3u;
    x = (x | (x << 2))  & 0x09249249u;
    return x;
}

static __device__ __forceinline__ uint32_t bin_of(float x, float y, float z) {
    const float sc = (float)GRID1D / 50.0f;
    int bx = (int)(x * sc), by = (int)(y * sc), bz = (int)(z * sc);
    bx = min(max(bx, 0), GRID1D - 1);
    by = min(max(by, 0), GRID1D - 1);
    bz = min(max(bz, 0), GRID1D - 1);
    return expand3((uint32_t)bx) | (expand3((uint32_t)by) << 1) | (expand3((uint32_t)bz) << 2);
}

__global__ void hist_kernel(const float* __restrict__ qp, int n) {
    int i = blockIdx.x * blockDim.x + threadIdx.x;
    if (i >= n) return;
    float x = qp[3 * i], y = qp[3 * i + 1], z = qp[3 * i + 2];
    atomicAdd(&g_hist[bin_of(x, y, z)], 1u);
}

// Per-superblock (2048 bins, pairwise: 2/thread) exclusive scan; the LAST block
// also computes the exclusive prefix over the 1024 superblock sums.
__global__ void __launch_bounds__(SCAN_THREADS) scan_blocks_kernel() {
    __shared__ uint32_t sh[SCAN_THREADS];
    __shared__ int is_last;
    int t = threadIdx.x;
    int base = blockIdx.x * SB_BINS;
    uint32_t v0 = g_hist[base + 2 * t];
    uint32_t v1 = g_hist[base + 2 * t + 1];
    sh[t] = v0 + v1;
    __syncthreads();
    #pragma unroll
    for (int off = 1; off < SCAN_THREADS; off <<= 1) {
        uint32_t add = (t >= off) ? sh[t - off] : 0u;
        __syncthreads();
        sh[t] += add;
        __syncthreads();
    }
    uint32_t excl_pair = sh[t] - v0 - v1;       // exclusive at bin 2t
    g_hist[base + 2 * t]     = excl_pair;
    g_hist[base + 2 * t + 1] = excl_pair + v0;

    // Writer of g_blocksum fences + signals (store->fence->atomic, same thread).
    if (t == SCAN_THREADS - 1) {
        g_blocksum[blockIdx.x] = sh[t];
        __threadfence();
        is_last = (atomicAdd(&g_done_counter, 1u) == (uint32_t)(SCAN_NBLK - 1));
    }
    __syncthreads();
    if (is_last) {
        __shared__ uint32_t bs[SCAN_NBLK];
        uint32_t bv = g_blocksum[t];
        bs[t] = bv;
        __syncthreads();
        #pragma unroll
        for (int off = 1; off < SCAN_NBLK; off <<= 1) {
            uint32_t add = (t >= off) ? bs[t - off] : 0u;
            __syncthreads();
            bs[t] += add;
            __syncthreads();
        }
        g_bsum_prefix[t] = bs[t] - bv;  // exclusive
    }
}

__global__ void scatter_kernel(const float* __restrict__ qp, int n) {
    int i = blockIdx.x * blockDim.x + threadIdx.x;
    if (i >= n) return;
    float x = qp[3 * i], y = qp[3 * i + 1], z = qp[3 * i + 2];
    uint32_t bin = bin_of(x, y, z);
    uint32_t pos = atomicAdd(&g_hist[bin], 1u) + __ldg(&g_bsum_prefix[bin >> 11]);
    g_qsort[pos] = make_float4(x, y, z, __int_as_float(i));
}

static __device__ __forceinline__ int probe(const int* __restrict__ htab,
                                            uint32_t key) {
    return __ldg(htab + (key & NHV_BMASK));
}

// One resolution level. GATE: probe 4 corners, test, then the other 4
// (pays only when lanes are spatially scattered, i.e. fine levels).
template <bool GATE>
static __device__ __forceinline__ void do_level(
    float sx, float sy, float sz,
    const int* __restrict__ htab,
    const float* __restrict__ ftab,
    float* __restrict__ acc)
{
    const float bx = floorf(sx), by = floorf(sy), bz = floorf(sz);
    const float tx = sx - bx, ty = sy - by, tz = sz - bz;

    const uint32_t ix = (uint32_t)(int)bx;
    const uint32_t iy = (uint32_t)(int)by;
    const uint32_t iz = (uint32_t)(int)bz;
    const uint32_t h0 = ix * P0 + iy * P1 + iz * P2;

    // corner k: key = h0 + (k&4 ? P0) + (k&2 ? P1) + (k&1 ? P2)
    int idx[8];
    if (GATE) {
        idx[0] = probe(htab, h0);
        idx[1] = probe(htab, h0 + P2);
        idx[2] = probe(htab, h0 + P1);
        idx[3] = probe(htab, h0 + P1 + P2);
        if ((idx[0] | idx[1] | idx[2] | idx[3]) < 0) return;
        idx[4] = probe(htab, h0 + P0);
        idx[5] = probe(htab, h0 + P0 + P2);
        idx[6] = probe(htab, h0 + P0 + P1);
        idx[7] = probe(htab, h0 + P0 + P1 + P2);
        if ((idx[4] | idx[5] | idx[6] | idx[7]) < 0) return;
    } else {
        #pragma unroll
        for (int k = 0; k < 8; k++) {
            uint32_t key = h0;
            if (k & 4) key += P0;
            if (k & 2) key += P1;
            if (k & 1) key += P2;
            idx[k] = probe(htab, key);
        }
        if ((idx[0] | idx[1] | idx[2] | idx[3] |
             idx[4] | idx[5] | idx[6] | idx[7]) < 0) return;
    }

    const float wxa[2] = { 1.f - tx, tx };
    const float wya[2] = { 1.f - ty, ty };
    const float wza[2] = { 1.f - tz, tz };

    #pragma unroll
    for (int k = 0; k < 8; k++) {
        const float w = wxa[(k >> 2) & 1] * wya[(k >> 1) & 1] * wza[k & 1];
        uint32_t id = (uint32_t)idx[k];
        id = (id < NHV_T) ? id : (NHV_T - 1u);
        const float4* fp = (const float4*)(ftab + ((size_t)id << 3));
        float4 a = __ldg(fp);
        float4 b = __ldg(fp + 1);
        acc[0] = fmaf(w, a.x, acc[0]);
        acc[1] = fmaf(w, a.y, acc[1]);
        acc[2] = fmaf(w, a.z, acc[2]);
        acc[3] = fmaf(w, a.w, acc[3]);
        acc[4] = fmaf(w, b.x, acc[4]);
        acc[5] = fmaf(w, b.y, acc[5]);
        acc[6] = fmaf(w, b.z, acc[6]);
        acc[7] = fmaf(w, b.w, acc[7]);
    }
}

__global__ void __launch_bounds__(256) nhv_kernel(
    const float* __restrict__ feats,
    const int*   __restrict__ fidx,
    float* __restrict__ out,
    int n_query)
{
    int i = blockIdx.x * blockDim.x + threadIdx.x;

    // Tail duty: re-zero sort state for the NEXT call/replay (grid-stride; safe:
    // runs after scatter; .bss guarantees zeros on the very first call).
    {
        int nt = gridDim.x * blockDim.x;
        for (int z = i; z < NBINS; z += nt) g_hist[z] = 0u;
        if (i == 0) g_done_counter = 0u;
    }

    if (i >= n_query) return;

    const float4 q = g_qsort[i];
    const uint32_t n = (uint32_t)__float_as_int(q.w);

    float acc[8] = {0.f, 0.f, 0.f, 0.f, 0.f, 0.f, 0.f, 0.f};

    const size_t HB = (size_t)NHV_B;
    const size_t FT = (size_t)NHV_T * 8;

    // lev 0..5, scale = 4 / 2^lev; GATE only on the scattered fine levels.
    do_level<true >(q.x * 4.f,    q.y * 4.f,    q.z * 4.f,    fidx,          feats,          acc);
    do_level<true >(q.x * 2.f,    q.y * 2.f,    q.z * 2.f,    fidx + HB,     feats + FT,     acc);
    do_level<false>(q.x * 1.f,    q.y * 1.f,    q.z * 1.f,    fidx + 2*HB,   feats + 2*FT,   acc);
    do_level<false>(q.x * 0.5f,   q.y * 0.5f,   q.z * 0.5f,   fidx + 3*HB,   feats + 3*FT,   acc);
    do_level<false>(q.x * 0.25f,  q.y * 0.25f,  q.z * 0.25f,  fidx + 4*HB,   feats + 4*FT,   acc);
    do_level<false>(q.x * 0.125f, q.y * 0.125f, q.z * 0.125f, fidx + 5*HB,   feats + 5*FT,   acc);

    float4* o = (float4*)(out + ((size_t)n << 3));
    o[0] = make_float4(acc[0], acc[1], acc[2], acc[3]);
    o[1] = make_float4(acc[4], acc[5], acc[6], acc[7]);
}

extern "C" void kernel_launch(void* const* d_in, const int* in_sizes, int n_in,
                              void* d_out, int out_size)
{
    const float* qp    = (const float*)d_in[0];
    const float* feats = (const float*)d_in[1];
    const int*   fidx  = (const int*)d_in[2];
    float* out = (float*)d_out;

    int n_query = in_sizes[0] / 3;
    int threads = 256;
    int blocks = (n_query + threads - 1) / threads;

    hist_kernel<<<blocks, threads>>>(qp, n_query);
    scan_blocks_kernel<<<SCAN_NBLK, SCAN_THREADS>>>();
    scatter_kernel<<<blocks, threads>>>(qp, n_query);
    nhv_kernel<<<blocks, threads>>>(feats, fidx, out, n_query);
}

// round 16
// speedup vs baseline: 1.1029x; 1.0833x over previous
#include <cuda_runtime.h>
#include <cstdint>

// NeuralHashVoxel: 64^3-Morton counting-sorted queries + PAIRWISE-INTERLEAVED
// level processing. Levels (0,1) gated 4-4 probing, levels (2,3) and (4,5)
// straight 8-probe; within each pair, both levels' probe rounds are issued
// before any consumption -> per-thread dependent-round depth ~15 -> ~8.
// [Converged facts: 64^3 bins (32^3 & 128^3 both worse), __ldg (ldcs worse),
//  4-4 gating fine levels only, occupancy not the binder.]
//
// Inputs: d_in[0] query_points f32 (N,3) in [0,50); d_in[1] features f32 (6,524288,8);
//         d_in[2] feature_indexs i32 (6,4194304) (-1 empty else [0,T)).
// Output: f32 (N,8).

#define NHV_L 6
#define NHV_T 524288
#define NHV_B 4194304u
#define NHV_BMASK 4194303u
#define P0 73856093u
#define P1 19349669u
#define P2 83492791u

#define NQ_MAX (1u << 20)
#define GRID1D 64
#define NBINS (GRID1D * GRID1D * GRID1D)     // 262144
#define SCAN_BLOCK_BINS 1024
#define SCAN_NBLK (NBINS / SCAN_BLOCK_BINS)  // 256

__device__ uint32_t g_hist[NBINS];
__device__ uint32_t g_blocksum[SCAN_NBLK];
__device__ uint32_t g_bsum_prefix[SCAN_NBLK];
__device__ uint32_t g_done_counter;
__device__ float4   g_qsort[NQ_MAX];           // xyz = point, w = orig index bits

static __device__ __forceinline__ uint32_t expand3(uint32_t x) {
    x &= 0x3FFu;
    x = (x | (x << 16)) & 0x030000FFu;
    x = (x | (x << 8))  & 0x0300F00Fu;
    x = (x | (x << 4))  & 0x030C30C3u;
    x = (x | (x << 2))  & 0x09249249u;
    return x;
}

static __device__ __forceinline__ uint32_t bin_of(float x, float y, float z) {
    const float sc = (float)GRID1D / 50.0f;
    int bx = (int)(x * sc), by = (int)(y * sc), bz = (int)(z * sc);
    bx = min(max(bx, 0), GRID1D - 1);
    by = min(max(by, 0), GRID1D - 1);
    bz = min(max(bz, 0), GRID1D - 1);
    return expand3((uint32_t)bx) | (expand3((uint32_t)by) << 1) | (expand3((uint32_t)bz) << 2);
}

__global__ void hist_kernel(const float* __restrict__ qp, int n) {
    int i = blockIdx.x * blockDim.x + threadIdx.x;
    if (i >= n) return;
    float x = qp[3 * i], y = qp[3 * i + 1], z = qp[3 * i + 2];
    atomicAdd(&g_hist[bin_of(x, y, z)], 1u);
}

__global__ void __launch_bounds__(SCAN_BLOCK_BINS) scan_blocks_kernel() {
    __shared__ uint32_t sh[SCAN_BLOCK_BINS];
    __shared__ int is_last;
    int t = threadIdx.x;
    int b = blockIdx.x * SCAN_BLOCK_BINS + t;
    uint32_t v = g_hist[b];
    sh[t] = v;
    __syncthreads();
    #pragma unroll
    for (int off = 1; off < SCAN_BLOCK_BINS; off <<= 1) {
        uint32_t add = (t >= off) ? sh[t - off] : 0u;
        __syncthreads();
        sh[t] += add;
        __syncthreads();
    }
    g_hist[b] = sh[t] - v;  // exclusive within superblock

    if (t == SCAN_BLOCK_BINS - 1) {
        g_blocksum[blockIdx.x] = sh[t];
        __threadfence();
        is_last = (atomicAdd(&g_done_counter, 1u) == (uint32_t)(SCAN_NBLK - 1));
    }
    __syncthreads();
    if (is_last) {
        __shared__ uint32_t bs[SCAN_NBLK];
        if (t < SCAN_NBLK) bs[t] = g_blocksum[t];
        __syncthreads();
        #pragma unroll
        for (int off = 1; off < SCAN_NBLK; off <<= 1) {
            uint32_t add = (t < SCAN_NBLK && t >= off) ? bs[t - off] : 0u;
            __syncthreads();
            if (t < SCAN_NBLK) bs[t] += add;
            __syncthreads();
        }
        if (t < SCAN_NBLK) g_bsum_prefix[t] = bs[t] - g_blocksum[t];
    }
}

__global__ void scatter_kernel(const float* __restrict__ qp, int n) {
    int i = blockIdx.x * blockDim.x + threadIdx.x;
    if (i >= n) return;
    float x = qp[3 * i], y = qp[3 * i + 1], z = qp[3 * i + 2];
    uint32_t bin = bin_of(x, y, z);
    uint32_t pos = atomicAdd(&g_hist[bin], 1u) + __ldg(&g_bsum_prefix[bin >> 10]);
    g_qsort[pos] = make_float4(x, y, z, __int_as_float(i));
}

static __device__ __forceinline__ int probe(const int* __restrict__ htab,
                                            uint32_t key) {
    return __ldg(htab + (key & NHV_BMASK));
}

// Gather + trilinear accumulate for one valid level.
static __device__ __forceinline__ void gather_acc(
    const int* __restrict__ idx,
    float tx, float ty, float tz,
    const float* __restrict__ ftab,
    float* __restrict__ acc)
{
    const float wxa[2] = { 1.f - tx, tx };
    const float wya[2] = { 1.f - ty, ty };
    const float wza[2] = { 1.f - tz, tz };
    #pragma unroll
    for (int k = 0; k < 8; k++) {
        const float w = wxa[(k >> 2) & 1] * wya[(k >> 1) & 1] * wza[k & 1];
        uint32_t id = (uint32_t)idx[k];
        id = (id < NHV_T) ? id : (NHV_T - 1u);
        const float4* fp = (const float4*)(ftab + ((size_t)id << 3));
        float4 a = __ldg(fp);
        float4 b = __ldg(fp + 1);
        acc[0] = fmaf(w, a.x, acc[0]);
        acc[1] = fmaf(w, a.y, acc[1]);
        acc[2] = fmaf(w, a.z, acc[2]);
        acc[3] = fmaf(w, a.w, acc[3]);
        acc[4] = fmaf(w, b.x, acc[4]);
        acc[5] = fmaf(w, b.y, acc[5]);
        acc[6] = fmaf(w, b.z, acc[6]);
        acc[7] = fmaf(w, b.w, acc[7]);
    }
}

// Two levels interleaved: all probe rounds issued before any consume.
// GATE: 4-then-4 staged probing per level (fine levels only).
template <bool GATE>
static __device__ __forceinline__ void do_pair(
    float sA, float sB,                   // the two levels' scales
    float qx, float qy, float qz,
    const int* __restrict__ hA, const int* __restrict__ hB,
    const float* __restrict__ fA, const float* __restrict__ fB,
    float* __restrict__ acc)
{
    const float sxa = qx * sA, sya = qy * sA, sza = qz * sA;
    const float sxb = qx * sB, syb = qy * sB, szb = qz * sB;
    const float bxa = floorf(sxa), bya = floorf(sya), bza = floorf(sza);
    const float bxb = floorf(sxb), byb = floorf(syb), bzb = floorf(szb);
    const uint32_t h0a = (uint32_t)(int)bxa * P0 + (uint32_t)(int)bya * P1
                       + (uint32_t)(int)bza * P2;
    const uint32_t h0b = (uint32_t)(int)bxb * P0 + (uint32_t)(int)byb * P1
                       + (uint32_t)(int)bzb * P2;

    int ia[8], ib[8];
    bool va, vb;
    if (GATE) {
        // Round 1 for BOTH levels (8 independent loads in flight).
        ia[0] = probe(hA, h0a);          ia[1] = probe(hA, h0a + P2);
        ia[2] = probe(hA, h0a + P1);     ia[3] = probe(hA, h0a + P1 + P2);
        ib[0] = probe(hB, h0b);          ib[1] = probe(hB, h0b + P2);
        ib[2] = probe(hB, h0b + P1);     ib[3] = probe(hB, h0b + P1 + P2);
        va = (ia[0] | ia[1] | ia[2] | ia[3]) >= 0;
        vb = (ib[0] | ib[1] | ib[2] | ib[3]) >= 0;
        if (!(va | vb)) return;
        // Round 2 for both (loads only; no consumption between the blocks).
        if (va) {
            ia[4] = probe(hA, h0a + P0);      ia[5] = probe(hA, h0a + P0 + P2);
            ia[6] = probe(hA, h0a + P0 + P1); ia[7] = probe(hA, h0a + P0 + P1 + P2);
        }
        if (vb) {
            ib[4] = probe(hB, h0b + P0);      ib[5] = probe(hB, h0b + P0 + P2);
            ib[6] = probe(hB, h0b + P0 + P1); ib[7] = probe(hB, h0b + P0 + P1 + P2);
        }
        if (va) va = (ia[4] | ia[5] | ia[6] | ia[7]) >= 0;
        if (vb) vb = (ib[4] | ib[5] | ib[6] | ib[7]) >= 0;
    } else {
        #pragma unroll
        for (int k = 0; k < 8; k++) {
            uint32_t key = h0a;
            if (k & 4) key += P0;
            if (k & 2) key += P1;
            if (k & 1) key += P2;
            ia[k] = probe(hA, key);
        }
        #pragma unroll
        for (int k = 0; k < 8; k++) {
            uint32_t key = h0b;
            if (k & 4) key += P0;
            if (k & 2) key += P1;
            if (k & 1) key += P2;
            ib[k] = probe(hB, key);
        }
        va = (ia[0] | ia[1] | ia[2] | ia[3] | ia[4] | ia[5] | ia[6] | ia[7]) >= 0;
        vb = (ib[0] | ib[1] | ib[2] | ib[3] | ib[4] | ib[5] | ib[6] | ib[7]) >= 0;
    }

    if (va) gather_acc(ia, sxa - bxa, sya - bya, sza - bza, fA, acc);
    if (vb) gather_acc(ib, sxb - bxb, syb - byb, szb - bzb, fB, acc);
}

__global__ void __launch_bounds__(256) nhv_kernel(
    const float* __restrict__ feats,
    const int*   __restrict__ fidx,
    float* __restrict__ out,
    int n_query)
{
    int i = blockIdx.x * blockDim.x + threadIdx.x;

    // Tail duty: re-zero sort state for the NEXT call/replay.
    if (i < NBINS) g_hist[i] = 0u;
    if (i == 0) g_done_counter = 0u;

    if (i >= n_query) return;

    const float4 q = g_qsort[i];
    const uint32_t n = (uint32_t)__float_as_int(q.w);

    float acc[8] = {0.f, 0.f, 0.f, 0.f, 0.f, 0.f, 0.f, 0.f};

    const size_t HB = (size_t)NHV_B;
    const size_t FT = (size_t)NHV_T * 8;

    do_pair<true >(4.f,   2.f,    q.x, q.y, q.z,
                   fidx,        fidx + HB,   feats,        feats + FT,   acc);
    do_pair<false>(1.f,   0.5f,   q.x, q.y, q.z,
                   fidx + 2*HB, fidx + 3*HB, feats + 2*FT, feats + 3*FT, acc);
    do_pair<false>(0.25f, 0.125f, q.x, q.y, q.z,
                   fidx + 4*HB, fidx + 5*HB, feats + 4*FT, feats + 5*FT, acc);

    float4* o = (float4*)(out + ((size_t)n << 3));
    o[0] = make_float4(acc[0], acc[1], acc[2], acc[3]);
    o[1] = make_float4(acc[4], acc[5], acc[6], acc[7]);
}

extern "C" void kernel_launch(void* const* d_in, const int* in_sizes, int n_in,
                              void* d_out, int out_size)
{
    const float* qp    = (const float*)d_in[0];
    const float* feats = (const float*)d_in[1];
    const int*   fidx  = (const int*)d_in[2];
    float* out = (float*)d_out;

    int n_query = in_sizes[0] / 3;
    int threads = 256;
    int blocks = (n_query + threads - 1) / threads;

    hist_kernel<<<blocks, threads>>>(qp, n_query);
    scan_blocks_kernel<<<SCAN_NBLK, SCAN_BLOCK_BINS>>>();
    scatter_kernel<<<blocks, threads>>>(qp, n_query);
    nhv_kernel<<<blocks, threads>>>(feats, fidx, out, n_query);
}